// round 4
// baseline (speedup 1.0000x reference)
#include <cuda_runtime.h>
#include <cstdint>

// ---------------------------------------------------------------------------
// ExpertGather: y[b,e,k,j] = sum_i x[b, Ind[b,e,k], i] * W[e,i,j]
// B=8, T=2048, I=1024, E=16, K=256, J=1024.  fp32 in/out.
// Safe baseline: legacy mma.sync m16n8k8 tf32, double-buffered smem,
// __syncthreads-only synchronization (cannot hang), index-masked (cannot OOB).
// ---------------------------------------------------------------------------

#define BB 8
#define TT 2048
#define II 1024
#define EE 16
#define KG 256
#define JJ 1024

#define TM 128
#define TN 128
#define TK 32
#define THREADS 256

#define ASTRIDE 36     // 32 + 4 pad (floats)
#define BSTRIDE 136    // 128 + 8 pad (floats)
#define A_BUF (TM * ASTRIDE)            // 4608 floats
#define B_BUF (TK * BSTRIDE)            // 4352 floats
#define SM_FLOATS (2 * A_BUF + 2 * B_BUF)   // 17920 floats = 71680 B

__device__ __forceinline__ uint32_t f2tf(float f) {
    uint32_t u;
    asm("cvt.rna.tf32.f32 %0, %1;" : "=r"(u) : "f"(f));
    return u;
}

__device__ __forceinline__ void mma_tf32(float* c, const uint32_t* a,
                                         const uint32_t* b) {
    asm volatile(
        "mma.sync.aligned.m16n8k8.row.col.f32.tf32.tf32.f32 "
        "{%0,%1,%2,%3}, {%4,%5,%6,%7}, {%8,%9}, {%0,%1,%2,%3};"
        : "+f"(c[0]), "+f"(c[1]), "+f"(c[2]), "+f"(c[3])
        : "r"(a[0]), "r"(a[1]), "r"(a[2]), "r"(a[3]),
          "r"(b[0]), "r"(b[1]));
}

__global__ void __launch_bounds__(THREADS, 2)
eg_kernel(const float* __restrict__ x, const float* __restrict__ W,
          const void* __restrict__ IndRaw, float* __restrict__ out)
{
    extern __shared__ __align__(16) float sm[];
    float* As0 = sm;
    float* As1 = sm + A_BUF;
    float* Bs0 = sm + 2 * A_BUF;
    float* Bs1 = sm + 2 * A_BUF + B_BUF;

    const int tid  = threadIdx.x;
    const int wid  = tid >> 5;
    const int lane = tid & 31;
    const int g    = lane >> 2;   // group id (0..7)
    const int tig  = lane & 3;    // thread-in-group (0..3)

    const int bid = blockIdx.x;
    const int nt = bid & 7;
    const int mt = (bid >> 3) & 1;
    const int e  = (bid >> 4) & 15;
    const int b  = bid >> 8;
    const int m0 = mt * TM;
    const int n0 = nt * TN;
    const int warpM = wid >> 2;   // 0..1
    const int warpN = wid & 3;    // 0..3

    // --- Ind dtype autodetect (reference says int64, JAX w/o x64 gives int32).
    // int64 values are in [0,2048) so every odd int32 word is 0.
    const int* ii = (const int*)IndRaw;
    const bool is64 = ((ii[1] | ii[3] | ii[5] | ii[7]) == 0);

    // A-row assignment: 2 threads per gathered row, 16 floats each.
    const int ar = tid >> 1;      // row 0..127
    const int ah = tid & 1;       // half selector
    const long long gidx = (long long)(b * EE + e) * KG + m0 + ar;
    long long t = is64 ? ((const long long*)IndRaw)[gidx] : (long long)ii[gidx];
    t &= (TT - 1);                // physically prevents OOB on x
    const float* arow = x + ((size_t)b * TT + (size_t)t) * II;
    const float* wbase = W + (size_t)e * II * JJ + n0;

    float acc[4][4][4];
    #pragma unroll
    for (int mf = 0; mf < 4; ++mf)
        #pragma unroll
        for (int nf = 0; nf < 4; ++nf)
            #pragma unroll
            for (int c = 0; c < 4; ++c) acc[mf][nf][c] = 0.0f;

    float4 aR[4], bR[4];

    // ---- global load of chunk kc into registers ----
    auto load_global = [&](int kc) {
        const float4* ap = (const float4*)(arow + kc * TK) + ah * 4;
        #pragma unroll
        for (int q = 0; q < 4; ++q) aR[q] = ap[q];
        #pragma unroll
        for (int it = 0; it < 4; ++it) {
            const int k = it * 8 + wid;                 // row within chunk
            bR[it] = *(const float4*)(wbase + (size_t)(kc * TK + k) * JJ
                                      + (lane << 2));
        }
    };
    // ---- convert + store into smem buffer ----
    auto store_smem = [&](float* A, float* B) {
        uint32_t* Au = (uint32_t*)A;
        uint32_t* Bu = (uint32_t*)B;
        #pragma unroll
        for (int q = 0; q < 4; ++q) {
            uint32_t* d = Au + ar * ASTRIDE + ah * 16 + q * 4;
            d[0] = f2tf(aR[q].x); d[1] = f2tf(aR[q].y);
            d[2] = f2tf(aR[q].z); d[3] = f2tf(aR[q].w);
        }
        #pragma unroll
        for (int it = 0; it < 4; ++it) {
            const int k = it * 8 + wid;
            uint32_t* d = Bu + k * BSTRIDE + (lane << 2);
            d[0] = f2tf(bR[it].x); d[1] = f2tf(bR[it].y);
            d[2] = f2tf(bR[it].z); d[3] = f2tf(bR[it].w);
        }
    };
    // ---- compute one K-chunk from smem buffer ----
    auto compute = [&](const float* A, const float* B) {
        const uint32_t* Au = (const uint32_t*)A;
        const uint32_t* Bu = (const uint32_t*)B;
        const int rbase = warpM * 64 + g;
        const int nbase = warpN * 32 + g;
        #pragma unroll
        for (int kk = 0; kk < 4; ++kk) {
            const int k = kk * 8 + tig;
            uint32_t af[4][4], bf[4][2];
            #pragma unroll
            for (int mf = 0; mf < 4; ++mf) {
                const int r = rbase + mf * 16;
                af[mf][0] = Au[r * ASTRIDE + k];
                af[mf][1] = Au[(r + 8) * ASTRIDE + k];
                af[mf][2] = Au[r * ASTRIDE + k + 4];
                af[mf][3] = Au[(r + 8) * ASTRIDE + k + 4];
            }
            #pragma unroll
            for (int nf = 0; nf < 4; ++nf) {
                const int n = nbase + nf * 8;
                bf[nf][0] = Bu[k * BSTRIDE + n];
                bf[nf][1] = Bu[(k + 4) * BSTRIDE + n];
            }
            #pragma unroll
            for (int mf = 0; mf < 4; ++mf)
                #pragma unroll
                for (int nf = 0; nf < 4; ++nf)
                    mma_tf32(acc[mf][nf], af[mf], bf[nf]);
        }
    };

    // ---- pipelined main loop: single __syncthreads per chunk ----
    load_global(0);
    store_smem(As0, Bs0);
    __syncthreads();

    #pragma unroll 1
    for (int kc = 0; kc < II / TK; ++kc) {
        const bool last = (kc == II / TK - 1);
        if (!last) load_global(kc + 1);
        if (kc & 1) compute(As1, Bs1);
        else        compute(As0, Bs0);
        if (!last) {
            if ((kc + 1) & 1) store_smem(As1, Bs1);
            else              store_smem(As0, Bs0);
        }
        __syncthreads();
    }

    // ---- epilogue: direct float2 stores ----
    const size_t rowbase = (size_t)((b * EE + e) * KG + m0);
    #pragma unroll
    for (int mf = 0; mf < 4; ++mf) {
        const int r0 = warpM * 64 + mf * 16 + g;
        #pragma unroll
        for (int nf = 0; nf < 4; ++nf) {
            const int c = n0 + warpN * 32 + nf * 8 + 2 * tig;
            float* p = out + (rowbase + r0) * JJ + c;
            *(float2*)p            = make_float2(acc[mf][nf][0], acc[mf][nf][1]);
            *(float2*)(p + 8 * JJ) = make_float2(acc[mf][nf][2], acc[mf][nf][3]);
        }
    }
}

extern "C" void kernel_launch(void* const* d_in, const int* in_sizes, int n_in,
                              void* d_out, int out_size) {
    const float* x   = (const float*)d_in[0];
    const float* W   = (const float*)d_in[1];
    const void*  Ind = d_in[2];
    float*       out = (float*)d_out;

    cudaFuncSetAttribute(eg_kernel, cudaFuncAttributeMaxDynamicSharedMemorySize,
                         SM_FLOATS * 4);

    const int grid = BB * EE * (KG / TM) * (JJ / TN);  // 8*16*2*8 = 2048
    eg_kernel<<<grid, THREADS, SM_FLOATS * 4>>>(x, W, Ind, out);
}